// round 4
// baseline (speedup 1.0000x reference)
#include <cuda_runtime.h>
#include <cstddef>

// Problem constants (match reference)
#define BATCH 256
#define SEQ   780
#define DIM   1024
#define MAXT  195
#define D4    (DIM / 4)   // 256 float4 lanes per row
#define THREADS 256

// Two pooled tokens per CTA: each thread front-batches up to 8 independent
// LDG.128 (4 per valid token) for deeper MLP, then 2 STG.128.
// Streaming hints (__ldcs/__stcs): no data here is ever reused — keep it
// evict-first so L2 stays a staging buffer, not a (useless) cache.
__global__ void __launch_bounds__(THREADS, 8)
avg_pool_merge2_kernel(const float* __restrict__ hs,
                       const int*   __restrict__ grid_thw,
                       float*       __restrict__ out,
                       float*       __restrict__ out_att)
{
    const int b  = blockIdx.y;
    const int jA = blockIdx.x * 2;      // always < MAXT (grid.x = ceil(MAXT/2))
    const int jB = jA + 1;
    const bool inB = (jB < MAXT);
    const int t  = threadIdx.x;         // float4 lane

    const int H2 = grid_thw[b * 3 + 1] >> 1;
    const int W2 = grid_thw[b * 3 + 2] >> 1;
    const int Hp = H2 >> 1;
    const int Wp = W2 >> 1;
    const int n_out = Hp * Wp;

    const bool validA = (jA < n_out);
    const bool validB = inB && (jB < n_out);

    const float4* __restrict__ src =
        reinterpret_cast<const float4*>(hs + (size_t)b * SEQ * DIM);
    float4* __restrict__ dst =
        reinterpret_cast<float4*>(out + (size_t)b * MAXT * DIM);

    // ---- address computation (both tokens) ----
    size_t baseA = 0, baseB = 0;
    if (validA) {
        const int r = jA / Wp;
        const int c = jA - r * Wp;
        baseA = (size_t)((2 * r) * W2 + 2 * c) * D4;
    }
    if (validB) {
        const int r = jB / Wp;
        const int c = jB - r * Wp;
        baseB = (size_t)((2 * r) * W2 + 2 * c) * D4;
    }
    const size_t rowW2 = (size_t)W2 * D4;

    // ---- front-batched loads: up to 8 independent LDG.128 in flight ----
    float4 a0, a1, a2, a3, b0, b1, b2, b3;
    if (validA) {
        const float4* p = src + baseA + t;
        a0 = __ldcs(p);
        a1 = __ldcs(p + D4);
        a2 = __ldcs(p + rowW2);
        a3 = __ldcs(p + rowW2 + D4);
    }
    if (validB) {
        const float4* p = src + baseB + t;
        b0 = __ldcs(p);
        b1 = __ldcs(p + D4);
        b2 = __ldcs(p + rowW2);
        b3 = __ldcs(p + rowW2 + D4);
    }

    // ---- compute + streaming stores ----
    float4 sA = make_float4(0.f, 0.f, 0.f, 0.f);
    if (validA) {
        sA.x = (a0.x + a1.x + a2.x + a3.x) * 0.25f;
        sA.y = (a0.y + a1.y + a2.y + a3.y) * 0.25f;
        sA.z = (a0.z + a1.z + a2.z + a3.z) * 0.25f;
        sA.w = (a0.w + a1.w + a2.w + a3.w) * 0.25f;
    }
    __stcs(dst + (size_t)jA * D4 + t, sA);

    if (inB) {
        float4 sB = make_float4(0.f, 0.f, 0.f, 0.f);
        if (validB) {
            sB.x = (b0.x + b1.x + b2.x + b3.x) * 0.25f;
            sB.y = (b0.y + b1.y + b2.y + b3.y) * 0.25f;
            sB.z = (b0.z + b1.z + b2.z + b3.z) * 0.25f;
            sB.w = (b0.w + b1.w + b2.w + b3.w) * 0.25f;
        }
        __stcs(dst + (size_t)jB * D4 + t, sB);
    }

    if (t == 0 && out_att) {
        out_att[(size_t)b * MAXT + jA] = validA ? 1.f : 0.f;
        if (inB) out_att[(size_t)b * MAXT + jB] = validB ? 1.f : 0.f;
    }
}

extern "C" void kernel_launch(void* const* d_in, const int* in_sizes, int n_in,
                              void* d_out, int out_size)
{
    const float* hs       = (const float*)d_in[0];  // [B, S, D] float32
    // d_in[1] = attention_mask (values unused by reference math)
    const int*   grid_thw = (const int*)d_in[2];    // [B, 3] int32

    float* out = (float*)d_out;
    const long long main_elems = (long long)BATCH * MAXT * DIM;
    const long long att_elems  = (long long)BATCH * MAXT;
    float* out_att = ((long long)out_size >= main_elems + att_elems)
                         ? out + main_elems : nullptr;

    dim3 grid((MAXT + 1) / 2, BATCH);
    avg_pool_merge2_kernel<<<grid, THREADS>>>(hs, grid_thw, out, out_att);
}

// round 5
// speedup vs baseline: 1.1826x; 1.1826x over previous
#include <cuda_runtime.h>
#include <cstddef>

// Problem constants (match reference)
#define BATCH 256
#define SEQ   780
#define DIM   1024
#define MAXT  195
#define D4    (DIM / 4)   // 256 float4 lanes per row
#define THREADS 256

__device__ __forceinline__ float4 ldcg_f4(const float4* p) {
    // L1-bypass global load (data is never reused; avoid L1 fill wavefronts)
    return __ldcg(p);
}

// One CTA per (batch, pooled-token) — the R3 shape that hit 79.6% DRAM.
// Valid tokens: gather 4 rows (4 independent LDG.128/thread), average, store.
// Invalid tokens: write a zero row (output buffer is poisoned, must write).
__global__ void __launch_bounds__(THREADS, 8)
avg_pool_merge_kernel(const float* __restrict__ hs,
                      const int*   __restrict__ grid_thw,
                      float*       __restrict__ out,
                      float*       __restrict__ out_att)
{
    const int j = blockIdx.x;   // pooled token index [0, MAXT)
    const int b = blockIdx.y;   // batch index
    const int t = threadIdx.x;  // float4 lane [0, 256)

    const int H2 = grid_thw[b * 3 + 1] >> 1;
    const int W2 = grid_thw[b * 3 + 2] >> 1;
    const int Hp = H2 >> 1;
    const int Wp = W2 >> 1;
    const int n_out = Hp * Wp;

    float4* o = reinterpret_cast<float4*>(
        out + ((size_t)b * MAXT + j) * DIM) + t;

    if (j >= n_out) {
        *o = make_float4(0.f, 0.f, 0.f, 0.f);
        if (t == 0 && out_att) out_att[(size_t)b * MAXT + j] = 0.f;
        return;
    }

    const int r = j / Wp;
    const int c = j - r * Wp;
    const int base = (2 * r) * W2 + 2 * c;  // top-left token of 2x2 window

    const float* srow = hs + (size_t)b * SEQ * DIM;
    const float4* p0 = reinterpret_cast<const float4*>(srow + (size_t)(base         ) * DIM) + t;
    const float4* p1 = reinterpret_cast<const float4*>(srow + (size_t)(base + 1     ) * DIM) + t;
    const float4* p2 = reinterpret_cast<const float4*>(srow + (size_t)(base + W2    ) * DIM) + t;
    const float4* p3 = reinterpret_cast<const float4*>(srow + (size_t)(base + W2 + 1) * DIM) + t;

    const float4 v0 = ldcg_f4(p0);
    const float4 v1 = ldcg_f4(p1);
    const float4 v2 = ldcg_f4(p2);
    const float4 v3 = ldcg_f4(p3);

    float4 s;
    s.x = (v0.x + v1.x + v2.x + v3.x) * 0.25f;
    s.y = (v0.y + v1.y + v2.y + v3.y) * 0.25f;
    s.z = (v0.z + v1.z + v2.z + v3.z) * 0.25f;
    s.w = (v0.w + v1.w + v2.w + v3.w) * 0.25f;
    *o = s;

    if (t == 0 && out_att) out_att[(size_t)b * MAXT + j] = 1.f;
}

extern "C" void kernel_launch(void* const* d_in, const int* in_sizes, int n_in,
                              void* d_out, int out_size)
{
    const float* hs       = (const float*)d_in[0];  // [B, S, D] float32
    // d_in[1] = attention_mask (values unused by reference math)
    const int*   grid_thw = (const int*)d_in[2];    // [B, 3] int32

    float* out = (float*)d_out;
    const long long main_elems = (long long)BATCH * MAXT * DIM;
    const long long att_elems  = (long long)BATCH * MAXT;
    float* out_att = ((long long)out_size >= main_elems + att_elems)
                         ? out + main_elems : nullptr;

    dim3 grid(MAXT, BATCH);
    avg_pool_merge_kernel<<<grid, THREADS>>>(hs, grid_thw, out, out_att);
}